// round 3
// baseline (speedup 1.0000x reference)
#include <cuda_runtime.h>
#include <cstdint>
#include <cstddef>

#define NPT 262144
#define C0  262144

// NEIG order: x fastest (-1,0,1), then y, then z
__constant__ int cNX[27] = {-1,0,1,-1,0,1,-1,0,1,-1,0,1,-1,0,1,-1,0,1,-1,0,1,-1,0,1,-1,0,1};
__constant__ int cNY[27] = {-1,-1,-1,0,0,0,1,1,1,-1,-1,-1,0,0,0,1,1,1,-1,-1,-1,0,0,0,1,1,1};
__constant__ int cNZ[27] = {-1,-1,-1,-1,-1,-1,-1,-1,-1,0,0,0,0,0,0,0,0,0,1,1,1,1,1,1,1,1,1};

struct GG {
    // ---------- zero block (memset each launch) ----------
    int   occ0[C0];
    int   cnt0[C0];
    int   cur0[C0];
    int   occL[37440];
    int   cntL[37440];
    int   curL[37440];
    float svraw[299584 * 10];
    int   zend[1];
    // ---------- rest ----------
    int   cid[NPT];
    int   rank0[C0];
    int   cstart0[C0];
    int   order0[NPT];
    int   seg0[NPT];
    int   pdeg[NPT];
    int   poff[NPT];
    int   neA[299584];      // ne0..ne4 at NEOFF
    int   rankL[37440];
    int   cstartL[37440];
    int   segL[299520];     // SOFF
    int   ordL[299520];
    int   ecnt[1011096];
    int   eoff[1011096];
    int   bsum[1024];
    int   tot[16];          // 0..4 = n_l, 5 = T, 6..10 = K_l
    int   mnb[3], mxb[3];
    float refv[3];
    float bnd[3 * 63];
    // output layout (computed on device)
    int oassign, osv, oedge, oids, A, S, E;
    int svb[5], ab[5], eb[5];
};
__device__ GG g;

// ------------------------------------------------------------------ scans
__device__ __forceinline__ int wscan(int x) {
    int lane = threadIdx.x & 31;
#pragma unroll
    for (int d = 1; d < 32; d <<= 1) {
        int y = __shfl_up_sync(0xffffffffu, x, d);
        if (lane >= d) x += y;
    }
    return x;
}

__global__ void k_scan_block(const int* __restrict__ in, int* __restrict__ out,
                             int* __restrict__ bs, int n) {
    int tid = threadIdx.x;
    int base = blockIdx.x * 1024 + tid * 4;
    int v0 = (base + 0 < n) ? in[base + 0] : 0;
    int v1 = (base + 1 < n) ? in[base + 1] : 0;
    int v2 = (base + 2 < n) ? in[base + 2] : 0;
    int v3 = (base + 3 < n) ? in[base + 3] : 0;
    int t = v0 + v1 + v2 + v3;
    int inc = wscan(t);
    __shared__ int ws[8];
    __shared__ int wo[8];
    if ((tid & 31) == 31) ws[tid >> 5] = inc;
    __syncthreads();
    if (tid == 0) {
        int s = 0;
        for (int i = 0; i < 8; i++) { int x = ws[i]; wo[i] = s; s += x; }
        ws[0] = s;
    }
    __syncthreads();
    int off = wo[tid >> 5] + inc - t;
    if (base + 0 < n) out[base + 0] = off;
    if (base + 1 < n) out[base + 1] = off + v0;
    if (base + 2 < n) out[base + 2] = off + v0 + v1;
    if (base + 3 < n) out[base + 3] = off + v0 + v1 + v2;
    if (tid == 0) bs[blockIdx.x] = ws[0];
}

__global__ void k_scan_bsum(int* bs, int nb, int* tot) {
    int tid = threadIdx.x;
    int x = (tid < nb) ? bs[tid] : 0;
    int inc = wscan(x);
    __shared__ int ws[32];
    __shared__ int wo[32];
    if ((tid & 31) == 31) ws[tid >> 5] = inc;
    __syncthreads();
    if (tid == 0) {
        int s = 0;
        for (int i = 0; i < 32; i++) { int v = ws[i]; wo[i] = s; s += v; }
        ws[0] = s;
    }
    __syncthreads();
    if (tid < nb) bs[tid] = wo[tid >> 5] + inc - x;
    if (tid == 0 && tot) *tot = ws[0];
}

__global__ void k_scan_add(int* out, const int* __restrict__ bs, int n) {
    int base = blockIdx.x * 1024 + threadIdx.x * 4;
    int a = bs[blockIdx.x];
#pragma unroll
    for (int j = 0; j < 4; j++)
        if (base + j < n) out[base + j] += a;
}

// ------------------------------------------------------------------ stage A
__global__ void k_init() {
    if (threadIdx.x < 3) { g.mnb[threadIdx.x] = 0x7f7fffff; g.mxb[threadIdx.x] = 0; }
}

__global__ void k_mmx(const float* __restrict__ nodes) {
    int t = blockIdx.x * blockDim.x + threadIdx.x;
    int i0 = t * 64;
    if (i0 >= NPT) return;
    int mn[3] = {0x7f7fffff, 0x7f7fffff, 0x7f7fffff};
    int mx[3] = {0, 0, 0};
    for (int i = i0; i < i0 + 64; i++) {
#pragma unroll
        for (int d = 0; d < 3; d++) {
            int b = __float_as_int(nodes[i * 10 + 4 + d]);
            mn[d] = min(mn[d], b);
            mx[d] = max(mx[d], b);
        }
    }
#pragma unroll
    for (int d = 0; d < 3; d++) {
        atomicMin(&g.mnb[d], mn[d]);
        atomicMax(&g.mxb[d], mx[d]);
    }
}

// exact sequential fp32 left fold per column (matches numpy axis-0 mean)
__global__ void k_fold(const float* __restrict__ nodes) {
    int d = threadIdx.x;
    if (d >= 3) return;
    const float* p = nodes + 4 + d;
    float s = 0.f;
#pragma unroll 8
    for (int i = 0; i < NPT; i++)
        s = __fadd_rn(s, __ldg(p + (size_t)i * 10));
    g.refv[d] = s * (1.0f / 262144.0f);  // exact power-of-two scale
}

// np.linspace under NumPy2 / NEP50 promotion: all float32
__global__ void k_bounds() {
    int i = threadIdx.x;  // 0..63
    float d0 = __fsub_rn(__int_as_float(g.mxb[0]), __int_as_float(g.mnb[0]));
    float d1 = __fsub_rn(__int_as_float(g.mxb[1]), __int_as_float(g.mnb[1]));
    float d2 = __fsub_rn(__int_as_float(g.mxb[2]), __int_as_float(g.mnb[2]));
    float box = fmaxf(d0, fmaxf(d1, d2));
    double half = (double)box * 0.5;
    float hf = (float)half;
    if (i >= 1 && i <= 63) {
#pragma unroll
        for (int d = 0; d < 3; d++) {
            float r = g.refv[d];
            float start = __fsub_rn(r, hf);
            float stop  = __fadd_rn(r, hf);
            float delta = __fsub_rn(stop, start);
            float step  = __fmul_rn(delta, 1.0f / 64.0f);  // exact /64
            float b = __fadd_rn(__fmul_rn((float)i, step), start);
            g.bnd[d * 63 + (i - 1)] = b;
        }
    }
}

__device__ __forceinline__ int ub63(const float* __restrict__ b, float v) {
    int lo = 0, hi = 63;
    while (lo < hi) {
        int m = (lo + hi) >> 1;
        if (b[m] <= v) lo = m + 1; else hi = m;
    }
    return lo;  // count of b <= v  (searchsorted side='right')
}

__global__ void k_cells(const float* __restrict__ nodes) {
    int i = blockIdx.x * blockDim.x + threadIdx.x;
    if (i >= NPT) return;
    float x = nodes[i * 10 + 4], y = nodes[i * 10 + 5], z = nodes[i * 10 + 6];
    int xg = ub63(g.bnd, x);
    int yg = 63 - ub63(g.bnd + 63, y);
    int zg = 63 - ub63(g.bnd + 126, z);
    int c = xg + (yg << 6) + (zg << 12);
    g.cid[i] = c;
    g.occ0[c] = 1;
    atomicAdd(&g.cnt0[c], 1);
}

__global__ void k_ne0() {
    int c = blockIdx.x * blockDim.x + threadIdx.x;
    if (c < C0 && g.occ0[c]) g.neA[g.rank0[c]] = c;
}

__global__ void k_scat0() {
    int i = blockIdx.x * blockDim.x + threadIdx.x;
    if (i >= NPT) return;
    int c = g.cid[i];
    int slot = g.cstart0[c] + atomicAdd(&g.cur0[c], 1);
    g.order0[slot] = i;
}

__global__ void k_sort0() {
    int c = blockIdx.x * blockDim.x + threadIdx.x;
    if (c >= C0) return;
    int n = g.cnt0[c];
    if (n < 2) return;
    int* a = g.order0 + g.cstart0[c];
    for (int i = 1; i < n; i++) {
        int v = a[i], j = i - 1;
        while (j >= 0 && a[j] > v) { a[j + 1] = a[j]; j--; }
        a[j + 1] = v;
    }
}

__global__ void k_seg0() {
    int i = blockIdx.x * blockDim.x + threadIdx.x;
    if (i < NPT) g.seg0[i] = g.rank0[g.cid[i]];
}

__global__ void k_pdeg() {
    int i = blockIdx.x * blockDim.x + threadIdx.x;
    if (i >= NPT) return;
    int c = g.cid[i];
    int x = c & 63, y = (c >> 6) & 63, z = c >> 12;
    int d = 0;
#pragma unroll
    for (int k = 0; k < 27; k++) {
        int nx = x + cNX[k], ny = y + cNY[k], nz = z + cNZ[k];
        if ((unsigned)nx < 64u && (unsigned)ny < 64u && (unsigned)nz < 64u)
            d += g.cnt0[nx + (ny << 6) + (nz << 12)];
    }
    g.pdeg[i] = d;
}

__global__ void k_gwrite(float* __restrict__ out) {
    int i = blockIdx.x * blockDim.x + threadIdx.x;
    if (i >= NPT) return;
    int T = g.tot[5];
    int c = g.cid[i];
    int x = c & 63, y = (c >> 6) & 63, z = c >> 12;
    int col = g.poff[i];
    float fi = (float)i;
    for (int k = 0; k < 27; k++) {
        int nx = x + cNX[k], ny = y + cNY[k], nz = z + cNZ[k];
        if ((unsigned)nx < 64u && (unsigned)ny < 64u && (unsigned)nz < 64u) {
            int cc = nx + (ny << 6) + (nz << 12);
            int n = g.cnt0[cc];
            if (n) {
                int b = g.cstart0[cc];
                for (int t = 0; t < n; t++) {
                    out[col] = (float)g.order0[b + t];
                    out[T + col] = fi;
                    col++;
                }
            }
        }
    }
}

// ------------------------------------------------------------------ levels
__global__ void k_loccup(const int* __restrict__ nePrev, int npIdx, int PG, int GL, int* occ) {
    int r = blockIdx.x * blockDim.x + threadIdx.x;
    if (r >= g.tot[npIdx]) return;
    int e = nePrev[r];
    int px = e % PG, py = (e / PG) % PG, pz = e / (PG * PG);
    occ[(px >> 1) + (py >> 1) * GL + (pz >> 1) * GL * GL] = 1;
}

__global__ void k_lne(const int* __restrict__ occ, const int* __restrict__ rank, int* ne, int GS) {
    int c = blockIdx.x * blockDim.x + threadIdx.x;
    if (c < GS && occ[c]) ne[rank[c]] = c;
}

__global__ void k_lseg(const int* __restrict__ nePrev, int npIdx, int PG, int GL,
                       const int* __restrict__ rank, int* seg, int* cnt) {
    int r = blockIdx.x * blockDim.x + threadIdx.x;
    if (r >= g.tot[npIdx]) return;
    int e = nePrev[r];
    int px = e % PG, py = (e / PG) % PG, pz = e / (PG * PG);
    int s = rank[(px >> 1) + (py >> 1) * GL + (pz >> 1) * GL * GL];
    seg[r] = s;
    atomicAdd(cnt + s, 1);
}

__global__ void k_lscat(const int* __restrict__ seg, int npIdx,
                        const int* __restrict__ cstart, int* cur, int* ord) {
    int r = blockIdx.x * blockDim.x + threadIdx.x;
    if (r >= g.tot[npIdx]) return;
    int s = seg[r];
    ord[cstart[s] + atomicAdd(cur + s, 1)] = r;
}

__global__ void k_lsort(const int* __restrict__ cnt, const int* __restrict__ cstart,
                        int* ord, int nIdx) {
    int s = blockIdx.x * blockDim.x + threadIdx.x;
    if (s >= g.tot[nIdx]) return;
    int n = cnt[s];
    if (n < 2) return;
    int* a = ord + cstart[s];
    for (int i = 1; i < n; i++) {
        int v = a[i], j = i - 1;
        while (j >= 0 && a[j] > v) { a[j + 1] = a[j]; j--; }
        a[j + 1] = v;
    }
}

// ------------------------------------------------------------------ edges
__global__ void k_ecnt(const int* __restrict__ occ, int CG, int FL, int* __restrict__ ecnt) {
    int idx = blockIdx.x * blockDim.x + threadIdx.x;
    int tot = CG * CG * CG * 27;
    if (idx >= tot) return;
    int q = idx / 27, k = idx - 27 * q;
    int qx = q % CG, qy = (q / CG) % CG, qz = q / (CG * CG);
    int ox = cNX[k], oy = cNY[k], oz = cNZ[k];
    int nx = qx + ox, ny = qy + oy, nz = qz + oz;
    int c = 0;
    if ((unsigned)nx < (unsigned)CG && (unsigned)ny < (unsigned)CG && (unsigned)nz < (unsigned)CG) {
        for (int a = 0; a < 8; a++) {
            int ax = a & 1, ay = (a >> 1) & 1, az = a >> 2;
            int fa = (2 * qx + ax) + (2 * qy + ay) * FL + (2 * qz + az) * FL * FL;
            if (!occ[fa]) continue;
            for (int b = 0; b < 8; b++) {
                int bx = b & 1, by = (b >> 1) & 1, bz = b >> 2;
                int dx = 2 * ox + bx - ax, dy = 2 * oy + by - ay, dz = 2 * oz + bz - az;
                if (dx > 1 || dx < -1 || dy > 1 || dy < -1 || dz > 1 || dz < -1) {
                    int fb = (2 * nx + bx) + (2 * ny + by) * FL + (2 * nz + bz) * FL * FL;
                    c += occ[fb];
                }
            }
        }
    }
    ecnt[idx] = c;
}

__global__ void k_ewrite(const int* __restrict__ occ, const int* __restrict__ rank,
                         int CG, int FL, const int* __restrict__ eoff, int lvl,
                         float* __restrict__ out) {
    int idx = blockIdx.x * blockDim.x + threadIdx.x;
    int tot = CG * CG * CG * 27;
    if (idx >= tot) return;
    int q = idx / 27, k = idx - 27 * q;
    int qx = q % CG, qy = (q / CG) % CG, qz = q / (CG * CG);
    int ox = cNX[k], oy = cNY[k], oz = cNZ[k];
    int nx = qx + ox, ny = qy + oy, nz = qz + oz;
    if (!((unsigned)nx < (unsigned)CG && (unsigned)ny < (unsigned)CG && (unsigned)nz < (unsigned)CG))
        return;
    int E = g.E;
    int base = g.oedge;
    int col = g.eb[lvl] + eoff[idx];
    for (int a = 0; a < 8; a++) {
        int ax = a & 1, ay = (a >> 1) & 1, az = a >> 2;
        int fa = (2 * qx + ax) + (2 * qy + ay) * FL + (2 * qz + az) * FL * FL;
        if (!occ[fa]) continue;
        float ra = (float)rank[fa];
        for (int b = 0; b < 8; b++) {
            int bx = b & 1, by = (b >> 1) & 1, bz = b >> 2;
            int dx = 2 * ox + bx - ax, dy = 2 * oy + by - ay, dz = 2 * oz + bz - az;
            if (dx > 1 || dx < -1 || dy > 1 || dy < -1 || dz > 1 || dz < -1) {
                int fb = (2 * nx + bx) + (2 * ny + by) * FL + (2 * nz + bz) * FL * FL;
                if (occ[fb]) {
                    out[base + col] = (float)rank[fb];   // row0 = dst rank
                    out[base + E + col] = ra;            // row1 = src rank
                    col++;
                }
            }
        }
    }
}

// ------------------------------------------------------------------ sv
__global__ void k_sv0(const float* __restrict__ nodes) {
    int i = blockIdx.x * blockDim.x + threadIdx.x;
    if (i >= NPT) return;
    int s = g.seg0[i];
    float m = nodes[i * 10];
    float* row = g.svraw + s * 10;
    atomicAdd(row, m);
#pragma unroll
    for (int j = 1; j < 10; j++)
        atomicAdd(row + j, m * nodes[i * 10 + j]);
}

__global__ void k_svnorm(int soff, int nIdx) {
    int r = blockIdx.x * blockDim.x + threadIdx.x;
    if (r >= g.tot[nIdx]) return;
    float* row = g.svraw + (size_t)(soff + r) * 10;
    float m = row[0];
#pragma unroll
    for (int j = 1; j < 10; j++) row[j] /= m;
}

__global__ void k_svagg(int soffP, int soffC, const int* __restrict__ seg, int npIdx) {
    int r = blockIdx.x * blockDim.x + threadIdx.x;
    if (r >= g.tot[npIdx]) return;
    const float* pr = g.svraw + (size_t)(soffP + r) * 10;
    float m = pr[0];
    int s = seg[r];
    float* row = g.svraw + (size_t)(soffC + s) * 10;
    atomicAdd(row, m);
#pragma unroll
    for (int j = 1; j < 10; j++)
        atomicAdd(row + j, m * pr[j]);
}

// ------------------------------------------------------------------ layout + writers
__global__ void k_off() {
    int n0 = g.tot[0], n1 = g.tot[1], n2 = g.tot[2], n3 = g.tot[3], n4 = g.tot[4];
    int T = g.tot[5];
    int K0 = g.tot[6], K1 = g.tot[7], K2 = g.tot[8], K3 = g.tot[9], K4 = g.tot[10];
    int A = NPT + n0 + n1 + n2 + n3;
    int S = n0 + n1 + n2 + n3 + n4;
    int E = K0 + K1 + K2 + K3 + K4;
    g.A = A; g.S = S; g.E = E;
    g.oassign = 2 * T;
    g.osv = 2 * T + 2 * A;
    g.oedge = g.osv + 10 * S;
    g.oids = g.oedge + 2 * E;
    g.svb[0] = 0; g.svb[1] = n0; g.svb[2] = n0 + n1; g.svb[3] = n0 + n1 + n2; g.svb[4] = n0 + n1 + n2 + n3;
    g.ab[0] = 0; g.ab[1] = NPT; g.ab[2] = NPT + n0; g.ab[3] = NPT + n0 + n1; g.ab[4] = NPT + n0 + n1 + n2;
    g.eb[0] = 0; g.eb[1] = K0; g.eb[2] = K0 + K1; g.eb[3] = K0 + K1 + K2; g.eb[4] = K0 + K1 + K2 + K3;
}

__global__ void k_awrite(const int* __restrict__ ord, const int* __restrict__ seg,
                         int cntIdx, int abIdx, float* __restrict__ out) {
    int t = blockIdx.x * blockDim.x + threadIdx.x;
    int n = (cntIdx < 0) ? NPT : g.tot[cntIdx];
    if (t >= n) return;
    int p = ord[t];
    int base = g.oassign + g.ab[abIdx];
    out[base + t] = (float)seg[p];
    out[base + g.A + t] = (float)p;
}

__global__ void k_svwrite(int soff, int nIdx, int lvl, float* __restrict__ out) {
    int gi = blockIdx.x * blockDim.x + threadIdx.x;
    if (gi >= g.tot[nIdx] * 10) return;
    out[g.osv + (size_t)g.svb[lvl] * 10 + gi] = g.svraw[(size_t)soff * 10 + gi];
}

__global__ void k_idwrite(const int* __restrict__ ne, int nIdx, int lvl, float* __restrict__ out) {
    int r = blockIdx.x * blockDim.x + threadIdx.x;
    if (r >= g.tot[nIdx]) return;
    out[g.oids + g.svb[lvl] + r] = (float)ne[r];
}

// ------------------------------------------------------------------ host
static void scan(int* in, int* out, int* bs, int* tot, int n) {
    int nb = (n + 1023) / 1024;
    k_scan_block<<<nb, 256>>>(in, out, bs, n);
    k_scan_bsum<<<1, 1024>>>(bs, nb, tot);
    k_scan_add<<<nb, 256>>>(out, bs, n);
}

extern "C" void kernel_launch(void* const* d_in, const int* in_sizes, int n_in,
                              void* d_out, int out_size) {
    const float* nodes = (const float*)d_in[0];
    float* out = (float*)d_out;
    GG* G;
    cudaGetSymbolAddress((void**)&G, g);

    cudaMemsetAsync(G, 0, offsetof(GG, zend), 0);
    k_init<<<1, 32>>>();
    k_mmx<<<16, 256>>>(nodes);
    k_fold<<<1, 32>>>(nodes);
    k_bounds<<<1, 64>>>();
    k_cells<<<NPT / 256, 256>>>(nodes);
    scan(G->occ0, G->rank0, G->bsum, &G->tot[0], C0);
    scan(G->cnt0, G->cstart0, G->bsum, nullptr, C0);
    k_ne0<<<C0 / 256, 256>>>();
    k_scat0<<<NPT / 256, 256>>>();
    k_sort0<<<C0 / 256, 256>>>();
    k_seg0<<<NPT / 256, 256>>>();
    k_pdeg<<<NPT / 256, 256>>>();
    scan(G->pdeg, G->poff, G->bsum, &G->tot[5], NPT);

    const int GL[4]   = {32, 16, 8, 4};
    const int PG[4]   = {64, 32, 16, 8};
    const int LOFF[4] = {0, 32768, 36864, 37376};
    const int GS[4]   = {32768, 4096, 512, 64};
    const int NEOFF[5] = {0, 262144, 294912, 299008, 299520};
    const int SOFF[4]  = {0, 262144, 294912, 299008};
    const int PMAX[4]  = {262144, 32768, 4096, 512};

    for (int l = 1; l <= 4; l++) {
        int li = l - 1;
        int* occ = G->occL + LOFF[li];
        int* rank = G->rankL + LOFF[li];
        int* cnt = G->cntL + LOFF[li];
        int* cst = G->cstartL + LOFF[li];
        int* cur = G->curL + LOFF[li];
        int* nePrev = G->neA + NEOFF[l - 1];
        int* ne = G->neA + NEOFF[l];
        int* seg = G->segL + SOFF[li];
        int* ord = G->ordL + SOFF[li];
        int pb = (PMAX[li] + 255) / 256;
        int gb = (GS[li] + 255) / 256;
        k_loccup<<<pb, 256>>>(nePrev, l - 1, PG[li], GL[li], occ);
        scan(occ, rank, G->bsum, &G->tot[l], GS[li]);
        k_lne<<<gb, 256>>>(occ, rank, ne, GS[li]);
        k_lseg<<<pb, 256>>>(nePrev, l - 1, PG[li], GL[li], rank, seg, cnt);
        scan(cnt, cst, G->bsum, nullptr, GS[li]);
        k_lscat<<<pb, 256>>>(seg, l - 1, cst, cur, ord);
        k_lsort<<<gb, 256>>>(cnt, cst, ord, l);
    }

    const int ECG[5] = {32, 16, 8, 4, 2};
    const int EFL[5] = {64, 32, 16, 8, 4};
    const int ESL[5] = {884736, 110592, 13824, 1728, 216};
    const int EOFFh[5] = {0, 884736, 995328, 1009152, 1010880};
    for (int l = 0; l < 5; l++) {
        const int* occ = (l == 0) ? G->occ0 : G->occL + LOFF[l - 1];
        int eb = (ESL[l] + 255) / 256;
        k_ecnt<<<eb, 256>>>(occ, ECG[l], EFL[l], G->ecnt + EOFFh[l]);
        scan(G->ecnt + EOFFh[l], G->eoff + EOFFh[l], G->bsum, &G->tot[6 + l], ESL[l]);
    }

    k_off<<<1, 1>>>();

    // supervoxel features
    k_sv0<<<NPT / 256, 256>>>(nodes);
    k_svnorm<<<(262144 + 255) / 256, 256>>>(NEOFF[0], 0);
    for (int l = 1; l <= 4; l++) {
        int li = l - 1;
        int pb = (PMAX[li] + 255) / 256;
        const int NMAXl[5] = {262144, 32768, 4096, 512, 64};
        k_svagg<<<pb, 256>>>(NEOFF[l - 1], NEOFF[l], G->segL + SOFF[li], l - 1);
        k_svnorm<<<(NMAXl[l] + 255) / 256, 256>>>(NEOFF[l], l);
    }

    // writers
    k_gwrite<<<NPT / 256, 256>>>(out);
    k_awrite<<<NPT / 256, 256>>>(G->order0, G->seg0, -1, 0, out);
    for (int l = 1; l <= 4; l++) {
        int li = l - 1;
        k_awrite<<<(PMAX[li] + 255) / 256, 256>>>(G->ordL + SOFF[li], G->segL + SOFF[li], l - 1, l, out);
    }
    const int NMAX[5] = {262144, 32768, 4096, 512, 64};
    for (int l = 0; l < 5; l++) {
        k_svwrite<<<(NMAX[l] * 10 + 255) / 256, 256>>>(NEOFF[l], l, l, out);
        k_idwrite<<<(NMAX[l] + 255) / 256, 256>>>(G->neA + NEOFF[l], l, l, out);
    }
    for (int l = 0; l < 5; l++) {
        const int* occ = (l == 0) ? G->occ0 : G->occL + LOFF[l - 1];
        const int* rank = (l == 0) ? G->rank0 : G->rankL + LOFF[l - 1];
        int eb = (ESL[l] + 255) / 256;
        k_ewrite<<<eb, 256>>>(occ, rank, ECG[l], EFL[l], G->eoff + EOFFh[l], l, out);
    }
    (void)in_sizes; (void)n_in; (void)out_size;
}

// round 4
// speedup vs baseline: 4.1266x; 4.1266x over previous
#include <cuda_runtime.h>
#include <cstdint>
#include <cstddef>

#define NPT 262144
#define C0  262144
#define FCH 2048

// NEIG order: x fastest (-1,0,1), then y, then z
__constant__ int cNX[27] = {-1,0,1,-1,0,1,-1,0,1,-1,0,1,-1,0,1,-1,0,1,-1,0,1,-1,0,1,-1,0,1};
__constant__ int cNY[27] = {-1,-1,-1,0,0,0,1,1,1,-1,-1,-1,0,0,0,1,1,1,-1,-1,-1,0,0,0,1,1,1};
__constant__ int cNZ[27] = {-1,-1,-1,-1,-1,-1,-1,-1,-1,0,0,0,0,0,0,0,0,0,1,1,1,1,1,1,1,1,1};

struct GG {
    // ---------- zero block (memset each launch) ----------
    int   occ0[C0];
    int   cnt0[C0];
    int   cur0[C0];
    int   occL[37440];
    int   cntL[37440];
    int   curL[37440];
    float svraw[299584 * 10];
    int   zend[1];
    // ---------- rest ----------
    int   cid[NPT];
    int   rank0[C0];
    int   cstart0[C0];
    int   order0[NPT];
    int   seg0[NPT];
    int   pdeg[NPT];
    int   poff[NPT];
    int   neA[299584];
    int   rankL[37440];
    int   cstartL[37440];
    int   segL[299520];
    int   ordL[299520];
    int   bsum[1024];
    int   bmask[216];
    int   tot[16];          // 0..4 = n_l, 5 = T, 6..10 = K_l
    int   mnb[3], mxb[3];
    float refv[3];
    float bnd[3 * 63];
    int oassign, osv, oedge, oids, A, S, E;
    int svb[5], ab[5], eb[5];
};
__device__ GG g;

__device__ __align__(16) int g_rinfo0[C0];
__device__ __align__(16) int g_rinfoL[37440];
__device__ int g_ecnt8[7077888];          // reused per edge level
__device__ int g_eoff8[8088768];          // per-level offsets, EOFF8 bases

// ------------------------------------------------------------------ scans
__device__ __forceinline__ int wscan(int x) {
    int lane = threadIdx.x & 31;
#pragma unroll
    for (int d = 1; d < 32; d <<= 1) {
        int y = __shfl_up_sync(0xffffffffu, x, d);
        if (lane >= d) x += y;
    }
    return x;
}

__global__ void k_scan_block(const int* __restrict__ in, int* __restrict__ out,
                             int* __restrict__ bs, int n) {
    int tid = threadIdx.x;                 // 1024 threads
    int base = blockIdx.x * 8192 + tid * 8;
    int v[8], t = 0;
#pragma unroll
    for (int j = 0; j < 8; j++) { v[j] = (base + j < n) ? in[base + j] : 0; t += v[j]; }
    int inc = wscan(t);
    __shared__ int ws[32], wo[32];
    if ((tid & 31) == 31) ws[tid >> 5] = inc;
    __syncthreads();
    if (tid == 0) {
        int s = 0;
        for (int i = 0; i < 32; i++) { int x = ws[i]; wo[i] = s; s += x; }
        ws[0] = s;
    }
    __syncthreads();
    int off = wo[tid >> 5] + inc - t;
#pragma unroll
    for (int j = 0; j < 8; j++) { if (base + j < n) out[base + j] = off; off += v[j]; }
    if (tid == 0) bs[blockIdx.x] = ws[0];
}

__global__ void k_scan_bsum(int* bs, int nb, int* tot) {
    int tid = threadIdx.x;
    int x = (tid < nb) ? bs[tid] : 0;
    int inc = wscan(x);
    __shared__ int ws[32], wo[32];
    if ((tid & 31) == 31) ws[tid >> 5] = inc;
    __syncthreads();
    if (tid == 0) {
        int s = 0;
        for (int i = 0; i < 32; i++) { int v = ws[i]; wo[i] = s; s += v; }
        ws[0] = s;
    }
    __syncthreads();
    if (tid < nb) bs[tid] = wo[tid >> 5] + inc - x;
    if (tid == 0 && tot) *tot = ws[0];
}

__global__ void k_scan_add(int* out, const int* __restrict__ bs, int n) {
    int base = blockIdx.x * 8192 + threadIdx.x * 8;
    int a = bs[blockIdx.x];
#pragma unroll
    for (int j = 0; j < 8; j++)
        if (base + j < n) out[base + j] += a;
}

// ------------------------------------------------------------------ stage A
__global__ void k_init() {
    if (threadIdx.x < 3) { g.mnb[threadIdx.x] = 0x7f7fffff; g.mxb[threadIdx.x] = 0; }
}

__global__ void k_masks() {
    int t = threadIdx.x;
    if (t >= 216) return;
    int k = t >> 3, a = t & 7;
    int ox = cNX[k], oy = cNY[k], oz = cNZ[k];
    int ax = a & 1, ay = (a >> 1) & 1, az = a >> 2;
    int m = 0;
    for (int b = 0; b < 8; b++) {
        int dx = 2 * ox + (b & 1) - ax;
        int dy = 2 * oy + ((b >> 1) & 1) - ay;
        int dz = 2 * oz + (b >> 2) - az;
        if (dx > 1 || dx < -1 || dy > 1 || dy < -1 || dz > 1 || dz < -1) m |= 1 << b;
    }
    g.bmask[t] = m;
}

__global__ void k_mmx(const float* __restrict__ nodes) {
    int t = blockIdx.x * blockDim.x + threadIdx.x;
    int i0 = t * 64;
    if (i0 >= NPT) return;
    int mn[3] = {0x7f7fffff, 0x7f7fffff, 0x7f7fffff};
    int mx[3] = {0, 0, 0};
    for (int i = i0; i < i0 + 64; i++) {
#pragma unroll
        for (int d = 0; d < 3; d++) {
            int b = __float_as_int(nodes[i * 10 + 4 + d]);
            mn[d] = min(mn[d], b);
            mx[d] = max(mx[d], b);
        }
    }
#pragma unroll
    for (int d = 0; d < 3; d++) {
        atomicMin(&g.mnb[d], mn[d]);
        atomicMax(&g.mxb[d], mx[d]);
    }
}

// exact sequential fp32 left fold per column, staged through shared memory.
// layout buf[2][FCH][3] -> folding lanes 0..2 read consecutive addrs (no bank conflict)
__global__ void __launch_bounds__(1024, 1) k_fold2(const float* __restrict__ nodes) {
    __shared__ float buf[2][FCH][3];
    int tid = threadIdx.x;
    // preload chunk 0 with all threads
    for (int e = tid; e < FCH; e += 1024) {
        buf[0][e][0] = nodes[e * 10 + 4];
        buf[0][e][1] = nodes[e * 10 + 5];
        buf[0][e][2] = nodes[e * 10 + 6];
    }
    __syncthreads();
    float s = 0.f;
    const int NCH = NPT / FCH;  // 128
    for (int c = 0; c < NCH; c++) {
        if (tid >= 32) {
            int cn = c + 1;
            if (cn < NCH) {
                int nb = cn & 1;
                int base = cn * FCH;
                for (int e = tid - 32; e < FCH; e += 992) {
                    buf[nb][e][0] = nodes[(base + e) * 10 + 4];
                    buf[nb][e][1] = nodes[(base + e) * 10 + 5];
                    buf[nb][e][2] = nodes[(base + e) * 10 + 6];
                }
            }
        } else if (tid < 3) {
            const float* bp = &buf[c & 1][0][tid];
#pragma unroll 8
            for (int e = 0; e < FCH; e++)
                s = __fadd_rn(s, bp[e * 3]);
        }
        __syncthreads();
    }
    if (tid < 3) g.refv[tid] = s * (1.0f / 262144.0f);
}

// np.linspace under NumPy2 / NEP50 promotion: all float32
__global__ void k_bounds() {
    int i = threadIdx.x;  // 0..63
    float d0 = __fsub_rn(__int_as_float(g.mxb[0]), __int_as_float(g.mnb[0]));
    float d1 = __fsub_rn(__int_as_float(g.mxb[1]), __int_as_float(g.mnb[1]));
    float d2 = __fsub_rn(__int_as_float(g.mxb[2]), __int_as_float(g.mnb[2]));
    float box = fmaxf(d0, fmaxf(d1, d2));
    double half = (double)box * 0.5;
    float hf = (float)half;
    if (i >= 1 && i <= 63) {
#pragma unroll
        for (int d = 0; d < 3; d++) {
            float r = g.refv[d];
            float start = __fsub_rn(r, hf);
            float stop  = __fadd_rn(r, hf);
            float delta = __fsub_rn(stop, start);
            float step  = __fmul_rn(delta, 1.0f / 64.0f);
            float b = __fadd_rn(__fmul_rn((float)i, step), start);
            g.bnd[d * 63 + (i - 1)] = b;
        }
    }
}

__device__ __forceinline__ int ub63(const float* __restrict__ b, float v) {
    int lo = 0, hi = 63;
    while (lo < hi) {
        int m = (lo + hi) >> 1;
        if (b[m] <= v) lo = m + 1; else hi = m;
    }
    return lo;
}

__global__ void k_cells(const float* __restrict__ nodes) {
    int i = blockIdx.x * blockDim.x + threadIdx.x;
    if (i >= NPT) return;
    float x = nodes[i * 10 + 4], y = nodes[i * 10 + 5], z = nodes[i * 10 + 6];
    int xg = ub63(g.bnd, x);
    int yg = 63 - ub63(g.bnd + 63, y);
    int zg = 63 - ub63(g.bnd + 126, z);
    int c = xg + (yg << 6) + (zg << 12);
    g.cid[i] = c;
    g.occ0[c] = 1;
    atomicAdd(&g.cnt0[c], 1);
}

__global__ void k_rpack(const int* __restrict__ occ, const int* __restrict__ rank,
                        int* __restrict__ rinfo, int n) {
    int i = blockIdx.x * blockDim.x + threadIdx.x;
    if (i < n) rinfo[i] = occ[i] ? rank[i] + 1 : 0;
}

__global__ void k_ne0() {
    int c = blockIdx.x * blockDim.x + threadIdx.x;
    if (c < C0 && g.occ0[c]) g.neA[g.rank0[c]] = c;
}

__global__ void k_scat0() {
    int i = blockIdx.x * blockDim.x + threadIdx.x;
    if (i >= NPT) return;
    int c = g.cid[i];
    int slot = g.cstart0[c] + atomicAdd(&g.cur0[c], 1);
    g.order0[slot] = i;
}

__global__ void k_sort0() {
    int c = blockIdx.x * blockDim.x + threadIdx.x;
    if (c >= C0) return;
    int n = g.cnt0[c];
    if (n < 2) return;
    int* a = g.order0 + g.cstart0[c];
    for (int i = 1; i < n; i++) {
        int v = a[i], j = i - 1;
        while (j >= 0 && a[j] > v) { a[j + 1] = a[j]; j--; }
        a[j + 1] = v;
    }
}

__global__ void k_seg0() {
    int i = blockIdx.x * blockDim.x + threadIdx.x;
    if (i < NPT) g.seg0[i] = g.rank0[g.cid[i]];
}

__global__ void k_pdeg() {
    int i = blockIdx.x * blockDim.x + threadIdx.x;
    if (i >= NPT) return;
    int c = g.cid[i];
    int x = c & 63, y = (c >> 6) & 63, z = c >> 12;
    int d = 0;
#pragma unroll
    for (int k = 0; k < 27; k++) {
        int nx = x + cNX[k], ny = y + cNY[k], nz = z + cNZ[k];
        if ((unsigned)nx < 64u && (unsigned)ny < 64u && (unsigned)nz < 64u)
            d += g.cnt0[nx + (ny << 6) + (nz << 12)];
    }
    g.pdeg[i] = d;
}

__global__ void k_gwrite(float* __restrict__ out) {
    int i = blockIdx.x * blockDim.x + threadIdx.x;
    if (i >= NPT) return;
    int T = g.tot[5];
    int c = g.cid[i];
    int x = c & 63, y = (c >> 6) & 63, z = c >> 12;
    int col = g.poff[i];
    float fi = (float)i;
    for (int k = 0; k < 27; k++) {
        int nx = x + cNX[k], ny = y + cNY[k], nz = z + cNZ[k];
        if ((unsigned)nx < 64u && (unsigned)ny < 64u && (unsigned)nz < 64u) {
            int cc = nx + (ny << 6) + (nz << 12);
            int n = g.cnt0[cc];
            if (n) {
                int b = g.cstart0[cc];
                for (int t = 0; t < n; t++) {
                    out[col] = (float)g.order0[b + t];
                    out[T + col] = fi;
                    col++;
                }
            }
        }
    }
}

// ------------------------------------------------------------------ levels
__global__ void k_loccup(const int* __restrict__ nePrev, int npIdx, int PG, int GL, int* occ) {
    int r = blockIdx.x * blockDim.x + threadIdx.x;
    if (r >= g.tot[npIdx]) return;
    int e = nePrev[r];
    int px = e % PG, py = (e / PG) % PG, pz = e / (PG * PG);
    occ[(px >> 1) + (py >> 1) * GL + (pz >> 1) * GL * GL] = 1;
}

__global__ void k_lne(const int* __restrict__ occ, const int* __restrict__ rank, int* ne, int GS) {
    int c = blockIdx.x * blockDim.x + threadIdx.x;
    if (c < GS && occ[c]) ne[rank[c]] = c;
}

__global__ void k_lseg(const int* __restrict__ nePrev, int npIdx, int PG, int GL,
                       const int* __restrict__ rank, int* seg, int* cnt) {
    int r = blockIdx.x * blockDim.x + threadIdx.x;
    if (r >= g.tot[npIdx]) return;
    int e = nePrev[r];
    int px = e % PG, py = (e / PG) % PG, pz = e / (PG * PG);
    int s = rank[(px >> 1) + (py >> 1) * GL + (pz >> 1) * GL * GL];
    seg[r] = s;
    atomicAdd(cnt + s, 1);
}

__global__ void k_lscat(const int* __restrict__ seg, int npIdx,
                        const int* __restrict__ cstart, int* cur, int* ord) {
    int r = blockIdx.x * blockDim.x + threadIdx.x;
    if (r >= g.tot[npIdx]) return;
    int s = seg[r];
    ord[cstart[s] + atomicAdd(cur + s, 1)] = r;
}

__global__ void k_lsort(const int* __restrict__ cnt, const int* __restrict__ cstart,
                        int* ord, int nIdx) {
    int s = blockIdx.x * blockDim.x + threadIdx.x;
    if (s >= g.tot[nIdx]) return;
    int n = cnt[s];
    if (n < 2) return;
    int* a = ord + cstart[s];
    for (int i = 1; i < n; i++) {
        int v = a[i], j = i - 1;
        while (j >= 0 && a[j] > v) { a[j + 1] = a[j]; j--; }
        a[j + 1] = v;
    }
}

// ------------------------------------------------------------------ edges (per q,k,a)
template<int CG, int FL>
__global__ void k_ecnt8(const int* __restrict__ rinfo, int* __restrict__ ecnt8) {
    int idx = blockIdx.x * 256 + threadIdx.x;
    if (idx >= CG * CG * CG * 216) return;
    int a = idx & 7, qk = idx >> 3;
    int k = qk % 27, q = qk / 27;
    int qx = q % CG, qy = (q / CG) % CG, qz = q / (CG * CG);
    int nx = qx + cNX[k], ny = qy + cNY[k], nz = qz + cNZ[k];
    int c = 0;
    if ((unsigned)nx < (unsigned)CG && (unsigned)ny < (unsigned)CG && (unsigned)nz < (unsigned)CG) {
        int fa = (2 * qx + (a & 1)) + (2 * qy + ((a >> 1) & 1)) * FL + (2 * qz + (a >> 2)) * FL * FL;
        if (__ldg(rinfo + fa)) {
            int m = g.bmask[idx & 215 ? ((k << 3) | a) : ((k << 3) | a)];
            m = g.bmask[(k << 3) | a];
            int bb = 2 * nx + 2 * ny * FL + 2 * nz * FL * FL;
            const int2* rp = (const int2*)rinfo;
            int2 r01 = __ldg(rp + (bb >> 1));
            int2 r23 = __ldg(rp + ((bb + FL) >> 1));
            int2 r45 = __ldg(rp + ((bb + FL * FL) >> 1));
            int2 r67 = __ldg(rp + ((bb + FL * FL + FL) >> 1));
            c  = ((m >> 0) & 1) & (r01.x != 0);
            c += ((m >> 1) & 1) & (r01.y != 0);
            c += ((m >> 2) & 1) & (r23.x != 0);
            c += ((m >> 3) & 1) & (r23.y != 0);
            c += ((m >> 4) & 1) & (r45.x != 0);
            c += ((m >> 5) & 1) & (r45.y != 0);
            c += ((m >> 6) & 1) & (r67.x != 0);
            c += ((m >> 7) & 1) & (r67.y != 0);
        }
    }
    ecnt8[idx] = c;
}

template<int CG, int FL>
__global__ void k_ewrite8(const int* __restrict__ rinfo, const int* __restrict__ eoff8,
                          int lvl, float* __restrict__ out) {
    int idx = blockIdx.x * 256 + threadIdx.x;
    if (idx >= CG * CG * CG * 216) return;
    int a = idx & 7, qk = idx >> 3;
    int k = qk % 27, q = qk / 27;
    int qx = q % CG, qy = (q / CG) % CG, qz = q / (CG * CG);
    int nx = qx + cNX[k], ny = qy + cNY[k], nz = qz + cNZ[k];
    if (!((unsigned)nx < (unsigned)CG && (unsigned)ny < (unsigned)CG && (unsigned)nz < (unsigned)CG))
        return;
    int fa = (2 * qx + (a & 1)) + (2 * qy + ((a >> 1) & 1)) * FL + (2 * qz + (a >> 2)) * FL * FL;
    int ra1 = __ldg(rinfo + fa);
    if (!ra1) return;
    float ra = (float)(ra1 - 1);
    int m = g.bmask[(k << 3) | a];
    int bb = 2 * nx + 2 * ny * FL + 2 * nz * FL * FL;
    const int2* rp = (const int2*)rinfo;
    int2 r01 = __ldg(rp + (bb >> 1));
    int2 r23 = __ldg(rp + ((bb + FL) >> 1));
    int2 r45 = __ldg(rp + ((bb + FL * FL) >> 1));
    int2 r67 = __ldg(rp + ((bb + FL * FL + FL) >> 1));
    int rv[8] = {r01.x, r01.y, r23.x, r23.y, r45.x, r45.y, r67.x, r67.y};
    int E = g.E;
    float* o0 = out + g.oedge + g.eb[lvl] + eoff8[idx];
#pragma unroll
    for (int b = 0; b < 8; b++) {
        if (((m >> b) & 1) && rv[b]) {
            o0[0] = (float)(rv[b] - 1);
            o0[E] = ra;
            o0++;
        }
    }
}

// ------------------------------------------------------------------ sv
__global__ void k_sv0(const float* __restrict__ nodes) {
    int i = blockIdx.x * blockDim.x + threadIdx.x;
    if (i >= NPT) return;
    int s = g.seg0[i];
    float m = nodes[i * 10];
    float* row = g.svraw + s * 10;
    atomicAdd(row, m);
#pragma unroll
    for (int j = 1; j < 10; j++)
        atomicAdd(row + j, m * nodes[i * 10 + j]);
}

__global__ void k_svnorm(int soff, int nIdx) {
    int r = blockIdx.x * blockDim.x + threadIdx.x;
    if (r >= g.tot[nIdx]) return;
    float* row = g.svraw + (size_t)(soff + r) * 10;
    float m = row[0];
#pragma unroll
    for (int j = 1; j < 10; j++) row[j] /= m;
}

__global__ void k_svagg(int soffP, int soffC, const int* __restrict__ seg, int npIdx) {
    int r = blockIdx.x * blockDim.x + threadIdx.x;
    if (r >= g.tot[npIdx]) return;
    const float* pr = g.svraw + (size_t)(soffP + r) * 10;
    float m = pr[0];
    int s = seg[r];
    float* row = g.svraw + (size_t)(soffC + s) * 10;
    atomicAdd(row, m);
#pragma unroll
    for (int j = 1; j < 10; j++)
        atomicAdd(row + j, m * pr[j]);
}

// ------------------------------------------------------------------ layout + writers
__global__ void k_off() {
    int n0 = g.tot[0], n1 = g.tot[1], n2 = g.tot[2], n3 = g.tot[3], n4 = g.tot[4];
    int T = g.tot[5];
    int K0 = g.tot[6], K1 = g.tot[7], K2 = g.tot[8], K3 = g.tot[9], K4 = g.tot[10];
    int A = NPT + n0 + n1 + n2 + n3;
    int S = n0 + n1 + n2 + n3 + n4;
    int E = K0 + K1 + K2 + K3 + K4;
    g.A = A; g.S = S; g.E = E;
    g.oassign = 2 * T;
    g.osv = 2 * T + 2 * A;
    g.oedge = g.osv + 10 * S;
    g.oids = g.oedge + 2 * E;
    g.svb[0] = 0; g.svb[1] = n0; g.svb[2] = n0 + n1; g.svb[3] = n0 + n1 + n2; g.svb[4] = n0 + n1 + n2 + n3;
    g.ab[0] = 0; g.ab[1] = NPT; g.ab[2] = NPT + n0; g.ab[3] = NPT + n0 + n1; g.ab[4] = NPT + n0 + n1 + n2;
    g.eb[0] = 0; g.eb[1] = K0; g.eb[2] = K0 + K1; g.eb[3] = K0 + K1 + K2; g.eb[4] = K0 + K1 + K2 + K3;
}

__global__ void k_awrite(const int* __restrict__ ord, const int* __restrict__ seg,
                         int cntIdx, int abIdx, float* __restrict__ out) {
    int t = blockIdx.x * blockDim.x + threadIdx.x;
    int n = (cntIdx < 0) ? NPT : g.tot[cntIdx];
    if (t >= n) return;
    int p = ord[t];
    int base = g.oassign + g.ab[abIdx];
    out[base + t] = (float)seg[p];
    out[base + g.A + t] = (float)p;
}

__global__ void k_svwrite(int soff, int nIdx, int lvl, float* __restrict__ out) {
    int gi = blockIdx.x * blockDim.x + threadIdx.x;
    if (gi >= g.tot[nIdx] * 10) return;
    out[g.osv + (size_t)g.svb[lvl] * 10 + gi] = g.svraw[(size_t)soff * 10 + gi];
}

__global__ void k_idwrite(const int* __restrict__ ne, int nIdx, int lvl, float* __restrict__ out) {
    int r = blockIdx.x * blockDim.x + threadIdx.x;
    if (r >= g.tot[nIdx]) return;
    out[g.oids + g.svb[lvl] + r] = (float)ne[r];
}

// ------------------------------------------------------------------ host
static void scan(int* in, int* out, int* bs, int* tot, int n) {
    int nb = (n + 8191) / 8192;
    k_scan_block<<<nb, 1024>>>(in, out, bs, n);
    k_scan_bsum<<<1, 1024>>>(bs, nb, tot);
    k_scan_add<<<nb, 1024>>>(out, bs, n);
}

extern "C" void kernel_launch(void* const* d_in, const int* in_sizes, int n_in,
                              void* d_out, int out_size) {
    const float* nodes = (const float*)d_in[0];
    float* out = (float*)d_out;
    GG* G;
    cudaGetSymbolAddress((void**)&G, g);
    int *rinfo0, *rinfoL, *ecnt8, *eoff8;
    cudaGetSymbolAddress((void**)&rinfo0, g_rinfo0);
    cudaGetSymbolAddress((void**)&rinfoL, g_rinfoL);
    cudaGetSymbolAddress((void**)&ecnt8, g_ecnt8);
    cudaGetSymbolAddress((void**)&eoff8, g_eoff8);

    cudaMemsetAsync(G, 0, offsetof(GG, zend), 0);
    k_init<<<1, 32>>>();
    k_masks<<<1, 256>>>();
    k_mmx<<<16, 256>>>(nodes);
    k_fold2<<<1, 1024>>>(nodes);
    k_bounds<<<1, 64>>>();
    k_cells<<<NPT / 256, 256>>>(nodes);
    scan(G->occ0, G->rank0, G->bsum, &G->tot[0], C0);
    scan(G->cnt0, G->cstart0, G->bsum, nullptr, C0);
    k_rpack<<<C0 / 256, 256>>>(G->occ0, G->rank0, rinfo0, C0);
    k_ne0<<<C0 / 256, 256>>>();
    k_scat0<<<NPT / 256, 256>>>();
    k_sort0<<<C0 / 256, 256>>>();
    k_seg0<<<NPT / 256, 256>>>();
    k_pdeg<<<NPT / 256, 256>>>();
    scan(G->pdeg, G->poff, G->bsum, &G->tot[5], NPT);

    const int GL[4]   = {32, 16, 8, 4};
    const int PG[4]   = {64, 32, 16, 8};
    const int LOFF[4] = {0, 32768, 36864, 37376};
    const int GS[4]   = {32768, 4096, 512, 64};
    const int NEOFF[5] = {0, 262144, 294912, 299008, 299520};
    const int SOFF[4]  = {0, 262144, 294912, 299008};
    const int PMAX[4]  = {262144, 32768, 4096, 512};

    for (int l = 1; l <= 4; l++) {
        int li = l - 1;
        int* occ = G->occL + LOFF[li];
        int* rank = G->rankL + LOFF[li];
        int* cnt = G->cntL + LOFF[li];
        int* cst = G->cstartL + LOFF[li];
        int* cur = G->curL + LOFF[li];
        int* nePrev = G->neA + NEOFF[l - 1];
        int* ne = G->neA + NEOFF[l];
        int* seg = G->segL + SOFF[li];
        int* ord = G->ordL + SOFF[li];
        int pb = (PMAX[li] + 255) / 256;
        int gb = (GS[li] + 255) / 256;
        k_loccup<<<pb, 256>>>(nePrev, l - 1, PG[li], GL[li], occ);
        scan(occ, rank, G->bsum, &G->tot[l], GS[li]);
        k_rpack<<<gb, 256>>>(occ, rank, rinfoL + LOFF[li], GS[li]);
        k_lne<<<gb, 256>>>(occ, rank, ne, GS[li]);
        k_lseg<<<pb, 256>>>(nePrev, l - 1, PG[li], GL[li], rank, seg, cnt);
        scan(cnt, cst, G->bsum, nullptr, GS[li]);
        k_lscat<<<pb, 256>>>(seg, l - 1, cst, cur, ord);
        k_lsort<<<gb, 256>>>(cnt, cst, ord, l);
    }

    // edge counts per (q,k,a) and offsets
    const int ESL8[5]  = {7077888, 884736, 110592, 13824, 1728};
    const int EOFF8[5] = {0, 7077888, 7962624, 8073216, 8087040};
    k_ecnt8<32, 64><<<(ESL8[0] + 255) / 256, 256>>>(rinfo0, ecnt8);
    scan(ecnt8, eoff8 + EOFF8[0], G->bsum, &G->tot[6], ESL8[0]);
    k_ecnt8<16, 32><<<(ESL8[1] + 255) / 256, 256>>>(rinfoL + LOFF[0], ecnt8);
    scan(ecnt8, eoff8 + EOFF8[1], G->bsum, &G->tot[7], ESL8[1]);
    k_ecnt8<8, 16><<<(ESL8[2] + 255) / 256, 256>>>(rinfoL + LOFF[1], ecnt8);
    scan(ecnt8, eoff8 + EOFF8[2], G->bsum, &G->tot[8], ESL8[2]);
    k_ecnt8<4, 8><<<(ESL8[3] + 255) / 256, 256>>>(rinfoL + LOFF[2], ecnt8);
    scan(ecnt8, eoff8 + EOFF8[3], G->bsum, &G->tot[9], ESL8[3]);
    k_ecnt8<2, 4><<<(ESL8[4] + 255) / 256, 256>>>(rinfoL + LOFF[3], ecnt8);
    scan(ecnt8, eoff8 + EOFF8[4], G->bsum, &G->tot[10], ESL8[4]);

    k_off<<<1, 1>>>();

    // supervoxel features
    k_sv0<<<NPT / 256, 256>>>(nodes);
    k_svnorm<<<(262144 + 255) / 256, 256>>>(NEOFF[0], 0);
    for (int l = 1; l <= 4; l++) {
        int li = l - 1;
        int pb = (PMAX[li] + 255) / 256;
        const int NMAXl[5] = {262144, 32768, 4096, 512, 64};
        k_svagg<<<pb, 256>>>(NEOFF[l - 1], NEOFF[l], G->segL + SOFF[li], l - 1);
        k_svnorm<<<(NMAXl[l] + 255) / 256, 256>>>(NEOFF[l], l);
    }

    // writers
    k_gwrite<<<NPT / 256, 256>>>(out);
    k_awrite<<<NPT / 256, 256>>>(G->order0, G->seg0, -1, 0, out);
    for (int l = 1; l <= 4; l++) {
        int li = l - 1;
        k_awrite<<<(PMAX[li] + 255) / 256, 256>>>(G->ordL + SOFF[li], G->segL + SOFF[li], l - 1, l, out);
    }
    const int NMAX[5] = {262144, 32768, 4096, 512, 64};
    for (int l = 0; l < 5; l++) {
        k_svwrite<<<(NMAX[l] * 10 + 255) / 256, 256>>>(NEOFF[l], l, l, out);
        k_idwrite<<<(NMAX[l] + 255) / 256, 256>>>(G->neA + NEOFF[l], l, l, out);
    }
    k_ewrite8<32, 64><<<(ESL8[0] + 255) / 256, 256>>>(rinfo0, eoff8 + EOFF8[0], 0, out);
    k_ewrite8<16, 32><<<(ESL8[1] + 255) / 256, 256>>>(rinfoL + LOFF[0], eoff8 + EOFF8[1], 1, out);
    k_ewrite8<8, 16><<<(ESL8[2] + 255) / 256, 256>>>(rinfoL + LOFF[1], eoff8 + EOFF8[2], 2, out);
    k_ewrite8<4, 8><<<(ESL8[3] + 255) / 256, 256>>>(rinfoL + LOFF[2], eoff8 + EOFF8[3], 3, out);
    k_ewrite8<2, 4><<<(ESL8[4] + 255) / 256, 256>>>(rinfoL + LOFF[3], eoff8 + EOFF8[4], 4, out);
    (void)in_sizes; (void)n_in; (void)out_size;
}

// round 6
// speedup vs baseline: 4.4035x; 1.0671x over previous
#include <cuda_runtime.h>
#include <cstdint>
#include <cstddef>

#define NPT 262144
#define C0  262144

// NEIG order: x fastest (-1,0,1), then y, then z
__constant__ int cNX[27] = {-1,0,1,-1,0,1,-1,0,1,-1,0,1,-1,0,1,-1,0,1,-1,0,1,-1,0,1,-1,0,1};
__constant__ int cNY[27] = {-1,-1,-1,0,0,0,1,1,1,-1,-1,-1,0,0,0,1,1,1,-1,-1,-1,0,0,0,1,1,1};
__constant__ int cNZ[27] = {-1,-1,-1,-1,-1,-1,-1,-1,-1,0,0,0,0,0,0,0,0,0,1,1,1,1,1,1,1,1,1};

struct GG {
    // ---------- zero block (memset each launch) ----------
    int   occ0[C0];
    int   cnt0[C0];
    int   cur0[C0];
    int   occL[37440];
    int   cntL[37440];
    int   curL[37440];
    float svraw[299584 * 10];
    int   tick[32];
    unsigned long long scanflags[2304];
    int   tot[16];          // 0..4 = n_l, 5 = T, 6..10 = K_l
    int   mnb[3], mxb[3];
    int   zend[1];
    // ---------- rest ----------
    int   cid[NPT];
    int   rank0[C0];
    int   cstart0[C0];
    int   order0[NPT];
    int   seg0[NPT];
    int   pdeg[NPT];
    int   poff[NPT];
    int   neA[299584];
    int   rankL[37440];
    int   cstartL[37440];
    int   segL[299520];
    int   ordL[299520];
    int   bmask[216];
    int   Stab[3 * 128 * 6];
    int   Ttab[3 * 128 * 6];
    float refv[3];
    float bnd[3 * 63];
    int oassign, osv, oedge, oids, A, S, E;
    int svb[5], ab[5], eb[5];
};
__device__ GG g;

__device__ __align__(16) int g_rinfo0[C0];
__device__ __align__(16) int g_rinfoL[37440];
__device__ int g_ecnt8[7077888];
__device__ int g_eoff8[8088768];

// ------------------------------------------------------------------ scan (single kernel, decoupled lookback)
__device__ __forceinline__ int wscan(int x) {
    int lane = threadIdx.x & 31;
#pragma unroll
    for (int d = 1; d < 32; d <<= 1) {
        int y = __shfl_up_sync(0xffffffffu, x, d);
        if (lane >= d) x += y;
    }
    return x;
}

__global__ void __launch_bounds__(512) k_scan1(const int* __restrict__ in, int* __restrict__ out,
                                               int n, int* tot, int ti, int fo) {
    __shared__ int sbid;
    __shared__ int wsum[16];
    __shared__ int woff[16];
    __shared__ int sexc;
    int tid = threadIdx.x;
    if (tid == 0) sbid = atomicAdd(&g.tick[ti], 1);
    __syncthreads();
    int bid = sbid;
    int base = bid * 4096 + tid * 8;
    int v[8], t = 0;
#pragma unroll
    for (int j = 0; j < 8; j++) { v[j] = (base + j < n) ? in[base + j] : 0; t += v[j]; }
    int inc = wscan(t);
    if ((tid & 31) == 31) wsum[tid >> 5] = inc;
    __syncthreads();
    if (tid == 0) {
        int s = 0;
        for (int i = 0; i < 16; i++) { int x = wsum[i]; woff[i] = s; s += x; }
        int B = s;
        unsigned long long* fl = g.scanflags + fo;
        int exc = 0;
        if (bid == 0) {
            atomicExch(&fl[0], (2ULL << 32) | (unsigned)B);
        } else {
            atomicExch(&fl[bid], (1ULL << 32) | (unsigned)B);
            int i = bid - 1;
            while (true) {
                unsigned long long w;
                do { w = atomicAdd(&fl[i], 0ULL); } while ((w >> 32) == 0ULL);
                exc += (int)(unsigned)w;
                if ((w >> 32) == 2ULL) break;
                i--;
            }
            atomicExch(&fl[bid], (2ULL << 32) | (unsigned)(exc + B));
        }
        sexc = exc;
        if (tot && bid == (int)gridDim.x - 1) *tot = exc + B;
    }
    __syncthreads();
    int off = sexc + woff[tid >> 5] + inc - t;
#pragma unroll
    for (int j = 0; j < 8; j++) { if (base + j < n) out[base + j] = off; off += v[j]; }
}

// ------------------------------------------------------------------ stage A
__global__ void k_init2() {
    int t = threadIdx.x;
    if (t < 3) { g.mnb[t] = 0x7f7fffff; g.mxb[t] = 0; }
    if (t < 216) {
        int k = t >> 3, a = t & 7;
        int ox = cNX[k], oy = cNY[k], oz = cNZ[k];
        int ax = a & 1, ay = (a >> 1) & 1, az = a >> 2;
        int m = 0;
        for (int b = 0; b < 8; b++) {
            int dx = 2 * ox + (b & 1) - ax;
            int dy = 2 * oy + ((b >> 1) & 1) - ay;
            int dz = 2 * oz + (b >> 2) - az;
            if (dx > 1 || dx < -1 || dy > 1 || dy < -1 || dz > 1 || dz < -1) m |= 1 << b;
        }
        g.bmask[t] = m;
    }
}

__global__ void k_mmx(const float* __restrict__ nodes) {
    int t = blockIdx.x * blockDim.x + threadIdx.x;
    int i0 = t * 64;
    if (i0 >= NPT) return;
    int mn[3] = {0x7f7fffff, 0x7f7fffff, 0x7f7fffff};
    int mx[3] = {0, 0, 0};
    for (int i = i0; i < i0 + 64; i++) {
#pragma unroll
        for (int d = 0; d < 3; d++) {
            int b = __float_as_int(nodes[i * 10 + 4 + d]);
            mn[d] = min(mn[d], b);
            mx[d] = max(mx[d], b);
        }
    }
#pragma unroll
    for (int d = 0; d < 3; d++) {
        atomicMin(&g.mnb[d], mn[d]);
        atomicMax(&g.mxb[d], mx[d]);
    }
}

// Precompute, for every chunk c (2048 elems) and binade k=12..17, the integer
// chunk-sum of RN-even(x / 2^(k-23)) plus an exact-tie flag. Within a binade,
// the exact fp32 sequential fold advances by exactly u * sum (no ties).
__global__ void __launch_bounds__(256) k_foldpre(const float* __restrict__ nodes) {
    int blk = blockIdx.x;             // 768 = c*6 + (k-12)
    int c = blk / 6, kk = blk % 6, kb = kk + 12;
    float scale = __int_as_float((23 - kb + 127) << 23);
    int t = threadIdx.x;
    int s0 = 0, s1 = 0, s2 = 0, tie = 0;
    for (int e = t; e < 2048; e += 256) {
        const float* p = nodes + ((size_t)c * 2048 + e) * 10 + 4;
        float v0 = __fmul_rn(__ldg(p + 0), scale);
        float v1 = __fmul_rn(__ldg(p + 1), scale);
        float v2 = __fmul_rn(__ldg(p + 2), scale);
        int q0 = __float2int_rn(v0), q1 = __float2int_rn(v1), q2 = __float2int_rn(v2);
        if (fabsf(__fsub_rn(v0, (float)q0)) == 0.5f) tie = 1;
        if (fabsf(__fsub_rn(v1, (float)q1)) == 0.5f) tie = 1;
        if (fabsf(__fsub_rn(v2, (float)q2)) == 0.5f) tie = 1;
        s0 += q0; s1 += q1; s2 += q2;
    }
    s0 = __reduce_add_sync(0xffffffffu, s0);
    s1 = __reduce_add_sync(0xffffffffu, s1);
    s2 = __reduce_add_sync(0xffffffffu, s2);
    tie = __any_sync(0xffffffffu, tie);
    __shared__ int sh[8][4];
    int wid = t >> 5;
    if ((t & 31) == 0) { sh[wid][0] = s0; sh[wid][1] = s1; sh[wid][2] = s2; sh[wid][3] = tie; }
    __syncthreads();
    if (t == 0) {
        int a0 = 0, a1 = 0, a2 = 0, tt = 0;
        for (int w = 0; w < 8; w++) { a0 += sh[w][0]; a1 += sh[w][1]; a2 += sh[w][2]; tt |= sh[w][3]; }
        g.Stab[(0 * 128 + c) * 6 + kk] = a0;
        g.Stab[(1 * 128 + c) * 6 + kk] = a1;
        g.Stab[(2 * 128 + c) * 6 + kk] = a2;
        g.Ttab[(0 * 128 + c) * 6 + kk] = tt;
        g.Ttab[(1 * 128 + c) * 6 + kk] = tt;
        g.Ttab[(2 * 128 + c) * 6 + kk] = tt;
    }
}

// Exact fp32 sequential left fold, chunk-stepped. One warp per dimension so
// fallback chunks in different dims don't serialize.
__global__ void k_fold3(const float* __restrict__ nodes) {
    if ((threadIdx.x & 31) != 0) return;
    int d = threadIdx.x >> 5;
    if (d >= 3) return;
    float s = 0.f;
    for (int c = 0; c < 128; c++) {
        int kb = (__float_as_int(s) >> 23) - 127;
        bool ok = false;
        float cand = 0.f;
        if (s > 0.f && kb >= 12 && kb <= 17) {
            int idx = (d * 128 + c) * 6 + (kb - 12);
            int S = g.Stab[idx];
            int tie = g.Ttab[idx];
            float u = __int_as_float((kb - 23 + 127) << 23);
            cand = __fadd_rn(s, __fmul_rn((float)S, u));  // exact while < 2^(kb+1)
            float lim = __int_as_float((kb + 1 + 127) << 23);
            if (!tie && __fadd_rn(cand, 4.0f) < lim) ok = true;
        }
        if (ok) {
            s = cand;
        } else {
            const float* p = nodes + (size_t)c * 2048 * 10 + 4 + d;
#pragma unroll 8
            for (int e = 0; e < 2048; e++)
                s = __fadd_rn(s, __ldg(p + e * 10));
        }
    }
    g.refv[d] = s * (1.0f / 262144.0f);
}

__global__ void k_bounds() {
    int i = threadIdx.x;  // 0..63
    float d0 = __fsub_rn(__int_as_float(g.mxb[0]), __int_as_float(g.mnb[0]));
    float d1 = __fsub_rn(__int_as_float(g.mxb[1]), __int_as_float(g.mnb[1]));
    float d2 = __fsub_rn(__int_as_float(g.mxb[2]), __int_as_float(g.mnb[2]));
    float box = fmaxf(d0, fmaxf(d1, d2));
    double half = (double)box * 0.5;
    float hf = (float)half;
    if (i >= 1 && i <= 63) {
#pragma unroll
        for (int d = 0; d < 3; d++) {
            float r = g.refv[d];
            float start = __fsub_rn(r, hf);
            float stop  = __fadd_rn(r, hf);
            float delta = __fsub_rn(stop, start);
            float step  = __fmul_rn(delta, 1.0f / 64.0f);
            float b = __fadd_rn(__fmul_rn((float)i, step), start);
            g.bnd[d * 63 + (i - 1)] = b;
        }
    }
}

__device__ __forceinline__ int ub63(const float* __restrict__ b, float v) {
    int lo = 0, hi = 63;
    while (lo < hi) {
        int m = (lo + hi) >> 1;
        if (b[m] <= v) lo = m + 1; else hi = m;
    }
    return lo;
}

__global__ void k_cells(const float* __restrict__ nodes) {
    int i = blockIdx.x * blockDim.x + threadIdx.x;
    if (i >= NPT) return;
    float x = nodes[i * 10 + 4], y = nodes[i * 10 + 5], z = nodes[i * 10 + 6];
    int xg = ub63(g.bnd, x);
    int yg = 63 - ub63(g.bnd + 63, y);
    int zg = 63 - ub63(g.bnd + 126, z);
    int c = xg + (yg << 6) + (zg << 12);
    g.cid[i] = c;
    g.occ0[c] = 1;
    atomicAdd(&g.cnt0[c], 1);
}

__global__ void k_post0() {
    int c = blockIdx.x * blockDim.x + threadIdx.x;
    if (c >= C0) return;
    int o = g.occ0[c];
    int r = g.rank0[c];
    g_rinfo0[c] = o ? r + 1 : 0;
    if (o) g.neA[r] = c;
}

__global__ void k_scat0() {
    int i = blockIdx.x * blockDim.x + threadIdx.x;
    if (i >= NPT) return;
    int c = g.cid[i];
    int slot = g.cstart0[c] + atomicAdd(&g.cur0[c], 1);
    g.order0[slot] = i;
}

__global__ void k_sort0() {
    int c = blockIdx.x * blockDim.x + threadIdx.x;
    if (c >= C0) return;
    int n = g.cnt0[c];
    if (n < 2) return;
    int* a = g.order0 + g.cstart0[c];
    for (int i = 1; i < n; i++) {
        int v = a[i], j = i - 1;
        while (j >= 0 && a[j] > v) { a[j + 1] = a[j]; j--; }
        a[j + 1] = v;
    }
}

__global__ void k_segpdeg() {
    int i = blockIdx.x * blockDim.x + threadIdx.x;
    if (i >= NPT) return;
    int c = g.cid[i];
    g.seg0[i] = g.rank0[c];
    int x = c & 63, y = (c >> 6) & 63, z = c >> 12;
    int d = 0;
#pragma unroll
    for (int k = 0; k < 27; k++) {
        int nx = x + cNX[k], ny = y + cNY[k], nz = z + cNZ[k];
        if ((unsigned)nx < 64u && (unsigned)ny < 64u && (unsigned)nz < 64u)
            d += g.cnt0[nx + (ny << 6) + (nz << 12)];
    }
    g.pdeg[i] = d;
}

__global__ void k_gwrite(float* __restrict__ out) {
    int i = blockIdx.x * blockDim.x + threadIdx.x;
    if (i >= NPT) return;
    int T = g.tot[5];
    int c = g.cid[i];
    int x = c & 63, y = (c >> 6) & 63, z = c >> 12;
    int col = g.poff[i];
    float fi = (float)i;
    for (int k = 0; k < 27; k++) {
        int nx = x + cNX[k], ny = y + cNY[k], nz = z + cNZ[k];
        if ((unsigned)nx < 64u && (unsigned)ny < 64u && (unsigned)nz < 64u) {
            int cc = nx + (ny << 6) + (nz << 12);
            int n = g.cnt0[cc];
            if (n) {
                int b = g.cstart0[cc];
                for (int t = 0; t < n; t++) {
                    out[col] = (float)g.order0[b + t];
                    out[T + col] = fi;
                    col++;
                }
            }
        }
    }
}

// ------------------------------------------------------------------ levels
__global__ void k_loccup(const int* __restrict__ nePrev, int npIdx, int PG, int GL, int* occ) {
    int r = blockIdx.x * blockDim.x + threadIdx.x;
    if (r >= g.tot[npIdx]) return;
    int e = nePrev[r];
    int px = e % PG, py = (e / PG) % PG, pz = e / (PG * PG);
    occ[(px >> 1) + (py >> 1) * GL + (pz >> 1) * GL * GL] = 1;
}

__global__ void k_lpost(const int* __restrict__ occ, const int* __restrict__ rank,
                        int* __restrict__ rinfo, int* __restrict__ ne, int GS) {
    int c = blockIdx.x * blockDim.x + threadIdx.x;
    if (c >= GS) return;
    int o = occ[c];
    int r = rank[c];
    rinfo[c] = o ? r + 1 : 0;
    if (o) ne[r] = c;
}

__global__ void k_lseg(const int* __restrict__ nePrev, int npIdx, int PG, int GL,
                       const int* __restrict__ rank, int* seg, int* cnt) {
    int r = blockIdx.x * blockDim.x + threadIdx.x;
    if (r >= g.tot[npIdx]) return;
    int e = nePrev[r];
    int px = e % PG, py = (e / PG) % PG, pz = e / (PG * PG);
    int s = rank[(px >> 1) + (py >> 1) * GL + (pz >> 1) * GL * GL];
    seg[r] = s;
    atomicAdd(cnt + s, 1);
}

__global__ void k_lscat(const int* __restrict__ seg, int npIdx,
                        const int* __restrict__ cstart, int* cur, int* ord) {
    int r = blockIdx.x * blockDim.x + threadIdx.x;
    if (r >= g.tot[npIdx]) return;
    int s = seg[r];
    ord[cstart[s] + atomicAdd(cur + s, 1)] = r;
}

__global__ void k_lsort(const int* __restrict__ cnt, const int* __restrict__ cstart,
                        int* ord, int nIdx) {
    int s = blockIdx.x * blockDim.x + threadIdx.x;
    if (s >= g.tot[nIdx]) return;
    int n = cnt[s];
    if (n < 2) return;
    int* a = ord + cstart[s];
    for (int i = 1; i < n; i++) {
        int v = a[i], j = i - 1;
        while (j >= 0 && a[j] > v) { a[j + 1] = a[j]; j--; }
        a[j + 1] = v;
    }
}

// ------------------------------------------------------------------ edges (per q,k,a)
template<int CG, int FL>
__global__ void k_ecnt8(const int* __restrict__ rinfo, int* __restrict__ ecnt8) {
    int idx = blockIdx.x * 256 + threadIdx.x;
    if (idx >= CG * CG * CG * 216) return;
    int a = idx & 7, qk = idx >> 3;
    int k = qk % 27, q = qk / 27;
    int qx = q % CG, qy = (q / CG) % CG, qz = q / (CG * CG);
    int nx = qx + cNX[k], ny = qy + cNY[k], nz = qz + cNZ[k];
    int c = 0;
    if ((unsigned)nx < (unsigned)CG && (unsigned)ny < (unsigned)CG && (unsigned)nz < (unsigned)CG) {
        int fa = (2 * qx + (a & 1)) + (2 * qy + ((a >> 1) & 1)) * FL + (2 * qz + (a >> 2)) * FL * FL;
        if (__ldg(rinfo + fa)) {
            int m = g.bmask[(k << 3) | a];
            int bb = 2 * nx + 2 * ny * FL + 2 * nz * FL * FL;
            const int2* rp = (const int2*)rinfo;
            int2 r01 = __ldg(rp + (bb >> 1));
            int2 r23 = __ldg(rp + ((bb + FL) >> 1));
            int2 r45 = __ldg(rp + ((bb + FL * FL) >> 1));
            int2 r67 = __ldg(rp + ((bb + FL * FL + FL) >> 1));
            c  = ((m >> 0) & 1) & (r01.x != 0);
            c += ((m >> 1) & 1) & (r01.y != 0);
            c += ((m >> 2) & 1) & (r23.x != 0);
            c += ((m >> 3) & 1) & (r23.y != 0);
            c += ((m >> 4) & 1) & (r45.x != 0);
            c += ((m >> 5) & 1) & (r45.y != 0);
            c += ((m >> 6) & 1) & (r67.x != 0);
            c += ((m >> 7) & 1) & (r67.y != 0);
        }
    }
    ecnt8[idx] = c;
}

template<int CG, int FL>
__global__ void k_ewrite8(const int* __restrict__ rinfo, const int* __restrict__ eoff8,
                          int lvl, float* __restrict__ out) {
    int idx = blockIdx.x * 256 + threadIdx.x;
    if (idx >= CG * CG * CG * 216) return;
    int a = idx & 7, qk = idx >> 3;
    int k = qk % 27, q = qk / 27;
    int qx = q % CG, qy = (q / CG) % CG, qz = q / (CG * CG);
    int nx = qx + cNX[k], ny = qy + cNY[k], nz = qz + cNZ[k];
    if (!((unsigned)nx < (unsigned)CG && (unsigned)ny < (unsigned)CG && (unsigned)nz < (unsigned)CG))
        return;
    int fa = (2 * qx + (a & 1)) + (2 * qy + ((a >> 1) & 1)) * FL + (2 * qz + (a >> 2)) * FL * FL;
    int ra1 = __ldg(rinfo + fa);
    if (!ra1) return;
    float ra = (float)(ra1 - 1);
    int m = g.bmask[(k << 3) | a];
    int bb = 2 * nx + 2 * ny * FL + 2 * nz * FL * FL;
    const int2* rp = (const int2*)rinfo;
    int2 r01 = __ldg(rp + (bb >> 1));
    int2 r23 = __ldg(rp + ((bb + FL) >> 1));
    int2 r45 = __ldg(rp + ((bb + FL * FL) >> 1));
    int2 r67 = __ldg(rp + ((bb + FL * FL + FL) >> 1));
    int rv[8] = {r01.x, r01.y, r23.x, r23.y, r45.x, r45.y, r67.x, r67.y};
    int E = g.E;
    float* o0 = out + g.oedge + g.eb[lvl] + eoff8[idx];
#pragma unroll
    for (int b = 0; b < 8; b++) {
        if (((m >> b) & 1) && rv[b]) {
            o0[0] = (float)(rv[b] - 1);
            o0[E] = ra;
            o0++;
        }
    }
}

// ------------------------------------------------------------------ sv (raw sums; normalization folded into output)
__global__ void k_sv0(const float* __restrict__ nodes) {
    int i = blockIdx.x * blockDim.x + threadIdx.x;
    if (i >= NPT) return;
    int s = g.seg0[i];
    float m = nodes[i * 10];
    float* row = g.svraw + (size_t)s * 10;
    atomicAdd(row, m);
#pragma unroll
    for (int j = 1; j < 10; j++)
        atomicAdd(row + j, m * nodes[i * 10 + j]);
}

__global__ void k_svagg(int soffP, int soffC, const int* __restrict__ seg, int npIdx) {
    int r = blockIdx.x * blockDim.x + threadIdx.x;
    if (r >= g.tot[npIdx]) return;
    const float* pr = g.svraw + (size_t)(soffP + r) * 10;
    float* row = g.svraw + (size_t)(soffC + seg[r]) * 10;
#pragma unroll
    for (int j = 0; j < 10; j++)
        atomicAdd(row + j, pr[j]);
}

// ------------------------------------------------------------------ layout + writers
__global__ void k_off() {
    int n0 = g.tot[0], n1 = g.tot[1], n2 = g.tot[2], n3 = g.tot[3], n4 = g.tot[4];
    int T = g.tot[5];
    int K0 = g.tot[6], K1 = g.tot[7], K2 = g.tot[8], K3 = g.tot[9], K4 = g.tot[10];
    int A = NPT + n0 + n1 + n2 + n3;
    int S = n0 + n1 + n2 + n3 + n4;
    int E = K0 + K1 + K2 + K3 + K4;
    g.A = A; g.S = S; g.E = E;
    g.oassign = 2 * T;
    g.osv = 2 * T + 2 * A;
    g.oedge = g.osv + 10 * S;
    g.oids = g.oedge + 2 * E;
    g.svb[0] = 0; g.svb[1] = n0; g.svb[2] = n0 + n1; g.svb[3] = n0 + n1 + n2; g.svb[4] = n0 + n1 + n2 + n3;
    g.ab[0] = 0; g.ab[1] = NPT; g.ab[2] = NPT + n0; g.ab[3] = NPT + n0 + n1; g.ab[4] = NPT + n0 + n1 + n2;
    g.eb[0] = 0; g.eb[1] = K0; g.eb[2] = K0 + K1; g.eb[3] = K0 + K1 + K2; g.eb[4] = K0 + K1 + K2 + K3;
}

__global__ void k_awriteAll(float* __restrict__ out) {
    int t = blockIdx.x * blockDim.x + threadIdx.x;
    if (t >= g.A) return;
    const int* ord; const int* seg; int loc;
    if (t < g.ab[1])      { ord = g.order0;          seg = g.seg0;            loc = t; }
    else if (t < g.ab[2]) { ord = g.ordL + 0;        seg = g.segL + 0;        loc = t - g.ab[1]; }
    else if (t < g.ab[3]) { ord = g.ordL + 262144;   seg = g.segL + 262144;   loc = t - g.ab[2]; }
    else if (t < g.ab[4]) { ord = g.ordL + 294912;   seg = g.segL + 294912;   loc = t - g.ab[3]; }
    else                  { ord = g.ordL + 299008;   seg = g.segL + 299008;   loc = t - g.ab[4]; }
    int p = ord[loc];
    out[g.oassign + t] = (float)seg[p];
    out[g.oassign + g.A + t] = (float)p;
}

__global__ void k_svidwrite(float* __restrict__ out) {
    int r = blockIdx.x * blockDim.x + threadIdx.x;
    if (r >= g.S) return;
    int neo;
    if (r < g.svb[1])      neo = 0;
    else if (r < g.svb[2]) neo = 262144 - g.svb[1];
    else if (r < g.svb[3]) neo = 294912 - g.svb[2];
    else if (r < g.svb[4]) neo = 299008 - g.svb[3];
    else                   neo = 299520 - g.svb[4];
    int loc = neo + r;   // NEOFF[lvl] + (r - svb[lvl])
    out[g.oids + r] = (float)g.neA[loc];
    const float* raw = g.svraw + (size_t)loc * 10;
    float m = raw[0];
    float* o = out + g.osv + (size_t)r * 10;
    o[0] = m;
#pragma unroll
    for (int j = 1; j < 10; j++) o[j] = raw[j] / m;
}

// ------------------------------------------------------------------ host
extern "C" void kernel_launch(void* const* d_in, const int* in_sizes, int n_in,
                              void* d_out, int out_size) {
    const float* nodes = (const float*)d_in[0];
    float* out = (float*)d_out;
    GG* G;
    cudaGetSymbolAddress((void**)&G, g);
    int *rinfo0, *rinfoL, *ecnt8, *eoff8;
    cudaGetSymbolAddress((void**)&rinfo0, g_rinfo0);
    cudaGetSymbolAddress((void**)&rinfoL, g_rinfoL);
    cudaGetSymbolAddress((void**)&ecnt8, g_ecnt8);
    cudaGetSymbolAddress((void**)&eoff8, g_eoff8);

    auto scan = [&](int* in, int* outp, int n, int* tot, int ti, int fo) {
        k_scan1<<<(n + 4095) / 4096, 512>>>(in, outp, n, tot, ti, fo);
    };

    cudaMemsetAsync(G, 0, offsetof(GG, zend), 0);
    k_init2<<<1, 256>>>();
    k_foldpre<<<768, 256>>>(nodes);
    k_mmx<<<16, 256>>>(nodes);
    k_fold3<<<1, 96>>>(nodes);
    k_bounds<<<1, 64>>>();
    k_cells<<<NPT / 256, 256>>>(nodes);
    scan(G->occ0, G->rank0, C0, &G->tot[0], 0, 0);
    scan(G->cnt0, G->cstart0, C0, nullptr, 1, 64);
    k_post0<<<C0 / 256, 256>>>();
    k_scat0<<<NPT / 256, 256>>>();
    k_sort0<<<C0 / 256, 256>>>();
    k_segpdeg<<<NPT / 256, 256>>>();
    scan(G->pdeg, G->poff, NPT, &G->tot[5], 2, 128);

    const int GL[4]    = {32, 16, 8, 4};
    const int PG[4]    = {64, 32, 16, 8};
    const int LOFF[4]  = {0, 32768, 36864, 37376};
    const int GS[4]    = {32768, 4096, 512, 64};
    const int NEOFF[5] = {0, 262144, 294912, 299008, 299520};
    const int SOFF[4]  = {0, 262144, 294912, 299008};
    const int PMAX[4]  = {262144, 32768, 4096, 512};
    const int OFO[4]   = {192, 200, 201, 202};
    const int CFO[4]   = {203, 211, 212, 213};

    for (int l = 1; l <= 4; l++) {
        int li = l - 1;
        int* occ = G->occL + LOFF[li];
        int* rank = G->rankL + LOFF[li];
        int* cnt = G->cntL + LOFF[li];
        int* cst = G->cstartL + LOFF[li];
        int* cur = G->curL + LOFF[li];
        int* nePrev = G->neA + NEOFF[l - 1];
        int* ne = G->neA + NEOFF[l];
        int* seg = G->segL + SOFF[li];
        int* ord = G->ordL + SOFF[li];
        int pb = (PMAX[li] + 255) / 256;
        int gb = (GS[li] + 255) / 256;
        k_loccup<<<pb, 256>>>(nePrev, l - 1, PG[li], GL[li], occ);
        scan(occ, rank, GS[li], &G->tot[l], 3 + li, OFO[li]);
        k_lpost<<<gb, 256>>>(occ, rank, rinfoL + LOFF[li], ne, GS[li]);
        k_lseg<<<pb, 256>>>(nePrev, l - 1, PG[li], GL[li], rank, seg, cnt);
        scan(cnt, cst, GS[li], nullptr, 7 + li, CFO[li]);
        k_lscat<<<pb, 256>>>(seg, l - 1, cst, cur, ord);
        k_lsort<<<gb, 256>>>(cnt, cst, ord, l);
    }

    const int ESL8[5]  = {7077888, 884736, 110592, 13824, 1728};
    const int EOFF8[5] = {0, 7077888, 7962624, 8073216, 8087040};
    const int EFO[5]   = {214, 1942, 2158, 2185, 2189};
    k_ecnt8<32, 64><<<(ESL8[0] + 255) / 256, 256>>>(rinfo0, ecnt8);
    scan(ecnt8, eoff8 + EOFF8[0], ESL8[0], &G->tot[6], 11, EFO[0]);
    k_ecnt8<16, 32><<<(ESL8[1] + 255) / 256, 256>>>(rinfoL + LOFF[0], ecnt8);
    scan(ecnt8, eoff8 + EOFF8[1], ESL8[1], &G->tot[7], 12, EFO[1]);
    k_ecnt8<8, 16><<<(ESL8[2] + 255) / 256, 256>>>(rinfoL + LOFF[1], ecnt8);
    scan(ecnt8, eoff8 + EOFF8[2], ESL8[2], &G->tot[8], 13, EFO[2]);
    k_ecnt8<4, 8><<<(ESL8[3] + 255) / 256, 256>>>(rinfoL + LOFF[2], ecnt8);
    scan(ecnt8, eoff8 + EOFF8[3], ESL8[3], &G->tot[9], 14, EFO[3]);
    k_ecnt8<2, 4><<<(ESL8[4] + 255) / 256, 256>>>(rinfoL + LOFF[3], ecnt8);
    scan(ecnt8, eoff8 + EOFF8[4], ESL8[4], &G->tot[10], 15, EFO[4]);

    k_off<<<1, 1>>>();

    k_sv0<<<NPT / 256, 256>>>(nodes);
    for (int l = 1; l <= 4; l++) {
        int li = l - 1;
        int pb = (PMAX[li] + 255) / 256;
        k_svagg<<<pb, 256>>>(NEOFF[l - 1], NEOFF[l], G->segL + SOFF[li], l - 1);
    }

    k_gwrite<<<NPT / 256, 256>>>(out);
    k_awriteAll<<<(NPT + 299520 + 255) / 256, 256>>>(out);
    k_svidwrite<<<(299584 + 255) / 256, 256>>>(out);
    k_ewrite8<32, 64><<<(ESL8[0] + 255) / 256, 256>>>(rinfo0, eoff8 + EOFF8[0], 0, out);
    k_ewrite8<16, 32><<<(ESL8[1] + 255) / 256, 256>>>(rinfoL + LOFF[0], eoff8 + EOFF8[1], 1, out);
    k_ewrite8<8, 16><<<(ESL8[2] + 255) / 256, 256>>>(rinfoL + LOFF[1], eoff8 + EOFF8[2], 2, out);
    k_ewrite8<4, 8><<<(ESL8[3] + 255) / 256, 256>>>(rinfoL + LOFF[2], eoff8 + EOFF8[3], 3, out);
    k_ewrite8<2, 4><<<(ESL8[4] + 255) / 256, 256>>>(rinfoL + LOFF[3], eoff8 + EOFF8[4], 4, out);
    (void)in_sizes; (void)n_in; (void)out_size;
}